// round 6
// baseline (speedup 1.0000x reference)
#include <cuda_runtime.h>
#include <cstdint>
#include <math.h>

#define T      1024
#define LRC    0.01f

// Scratch (device globals — allocation is forbidden)
__device__ float g_cw[16 * T];      // control weights [rs, n]
__device__ float g_epart[32];       // 8 cluster ranks x 4 e partials

// ---------------------------------------------------------------------------
// k1 (8-CTA cluster, 256 thr/CTA): fused err + cw.
// Fires the PDL trigger immediately so k2 can start staging Fx in parallel.
// ---------------------------------------------------------------------------
__global__ void __cluster_dims__(8, 1, 1) k1(const float* __restrict__ Fx,
                                             const float* __restrict__ Dis,
                                             const float* __restrict__ w0) {
    asm volatile("griddepcontrol.launch_dependents;");

    const int tid  = threadIdx.x;
    const int rank = blockIdx.x;
    const float4* w4  = (const float4*)w0;
    const float4* fx4 = (const float4*)Fx;

    float acc[4] = {0.f, 0.f, 0.f, 0.f};
#pragma unroll
    for (int s = 0; s < 2; s++) {
        const int i4 = rank * 512 + s * 256 + tid;    // float4 index into w0
        const float4 w = w4[i4];
        const int rs = i4 >> 8, n4 = i4 & 255;
#pragma unroll
        for (int e = 0; e < 4; e++) {
            const float4 x = fx4[(rs << 10) + (e << 8) + n4];
            acc[e] += x.x * w.x + x.y * w.y + x.z * w.z + x.w * w.w;
        }
    }
#pragma unroll
    for (int o = 16; o; o >>= 1)
#pragma unroll
        for (int e = 0; e < 4; e++) acc[e] += __shfl_xor_sync(0xffffffffu, acc[e], o);

    __shared__ float sp[8][4];
    __shared__ float serr[4];
    if ((tid & 31) == 0)
#pragma unroll
        for (int e = 0; e < 4; e++) sp[tid >> 5][e] = acc[e];
    __syncthreads();
    if (tid < 4) {
        float s = 0.f;
#pragma unroll
        for (int wq = 0; wq < 8; wq++) s += sp[wq][tid];
        g_epart[rank * 4 + tid] = s;
    }

    asm volatile("barrier.cluster.arrive.release.aligned;" ::: "memory");
    asm volatile("barrier.cluster.wait.acquire.aligned;"   ::: "memory");

    if (tid < 4) {
        volatile const float* gp = g_epart;
        float s = 0.f;
#pragma unroll
        for (int r = 0; r < 8; r++) s += gp[r * 4 + tid];
        serr[tid] = Dis[tid * T + (T - 1)] - s;
    }
    __syncthreads();
    const float e0 = serr[0], e1 = serr[1], e2 = serr[2], e3 = serr[3];

    float4* cw4 = (float4*)g_cw;
#pragma unroll
    for (int s = 0; s < 2; s++) {
        const int i4 = rank * 512 + s * 256 + tid;
        float4 c = w4[i4];
        const int rs = i4 >> 8, n4 = i4 & 255;
        const float4 x0 = fx4[(rs << 10) + (0 << 8) + n4];
        const float4 x1 = fx4[(rs << 10) + (1 << 8) + n4];
        const float4 x2 = fx4[(rs << 10) + (2 << 8) + n4];
        const float4 x3 = fx4[(rs << 10) + (3 << 8) + n4];
        c.x += LRC * (x0.x * e0 + x1.x * e1 + x2.x * e2 + x3.x * e3);
        c.y += LRC * (x0.y * e0 + x1.y * e1 + x2.y * e2 + x3.y * e3);
        c.z += LRC * (x0.z * e0 + x1.z * e1 + x2.z * e2 + x3.z * e3);
        c.w += LRC * (x0.w * e0 + x1.w * e1 + x2.w * e2 + x3.w * e3);
        cw4[i4] = c;
    }
}

// ---------------------------------------------------------------------------
// k2: causal correlation + output + gamma.
// grid (32 pair-tiles, 4 e, 2 rs-halves), cluster (1,1,2), 320 thr, 66 KB smem,
// 2 CTAs/SM. Compute loop is 2-stage software-pipelined: qq+1's smem loads
// are issued before qq's 64-FMA block, hiding LDS latency behind FMAs.
// ---------------------------------------------------------------------------
#define SFQ   1048            // sF row stride in floats (20 pad + 1024 + 4 tail)
#define NF4   262             // float4 per sF row
#define SWOFF (8 * SFQ)       // 8384: start of cw rows (8 rows of 1024)

extern __shared__ float smem[];

__global__ void __launch_bounds__(320, 2) __cluster_dims__(1, 1, 2)
k2(const float* __restrict__ Fx, float* __restrict__ out) {
    __shared__ float s2[32][8];
    __shared__ float sXfer[32];

    const int tid  = threadIdx.x;
    const int b    = blockIdx.x;
    const int e    = blockIdx.y;
    const int half = blockIdx.z;                    // rs-half = cluster rank
    const int t0A = b << 4, t0B = (63 - b) << 4;
    const int cA = (t0A + 16) >> 2;                 // 4..128 chunks for tile A
    const int cB = 260 - cA;                        // chunks for tile B
    const bool active = tid < 260;
    const bool isA = tid < cA;
    const int t0 = isA ? t0A : t0B;
    const int nb = (isA ? tid : (tid - cA)) << 2;   // n-chunk base
    const int ab = 16 + t0 - nb;                    // aligned sF read base

    const float4 z4 = make_float4(0.f, 0.f, 0.f, 0.f);

    // ---- stage this half's 8 Fx rows (front zero-padded) — k1-independent ----
    float4* dF = (float4*)smem;
    for (int idx = tid; idx < 8 * NF4; idx += 320) {
        const int qq = idx / NF4, i = idx - qq * NF4;
        const int rs = (half << 3) + qq;
        float4 v = z4;
        if (i >= 5 && i < 261)
            v = ((const float4*)(Fx + (((rs << 2) + e) << 10)))[i - 5];
        dF[qq * NF4 + i] = v;
    }

    // gamma vector — also k1-independent, do it before the PDL wait
    if (half == 0 && e == 0 && tid >= 32 && tid < 64) {
        const int j = tid - 32;
        const int t = (j < 16) ? (t0A + j) : (t0B + j - 16);
        out[4096 + t] = powf(0.999f, (float)(1023 - t));
    }

    // ---- wait for k1's g_cw, then stage this half's 8 cw rows ----
    asm volatile("griddepcontrol.wait;" ::: "memory");
    float4* dW = (float4*)(smem + SWOFF);
    const float4* ws = (const float4*)(g_cw + (half << 3 << 10));
    for (int idx = tid; idx < 8 * 256; idx += 320)
        dW[idx] = ws[idx];
    __syncthreads();

    // ---- compute: software-pipelined over qq (8 rs rows) ----
    float acc[16];
#pragma unroll
    for (int j = 0; j < 16; j++) acc[j] = 0.f;

    if (active) {
        const float* wBase = &smem[SWOFF + nb];
        const float* fBase = &smem[ab];

        float4 wv = *(const float4*)wBase;
        float4 Fv[6];
        {
            const float4* F4 = (const float4*)fBase;
#pragma unroll
            for (int m = 0; m < 6; m++) Fv[m] = F4[m];
        }

#pragma unroll
        for (int qq = 0; qq < 8; qq++) {
            float4 wn = z4;
            float4 Fn[6];
            if (qq < 7) {                       // prefetch next rs row
                wn = *(const float4*)(wBase + ((qq + 1) << 10));
                const float4* Fp = (const float4*)(fBase + (qq + 1) * SFQ);
#pragma unroll
                for (int m = 0; m < 6; m++) Fn[m] = Fp[m];
            }
            float ff[24];
#pragma unroll
            for (int m = 0; m < 6; m++) {
                ff[4 * m + 0] = Fv[m].x; ff[4 * m + 1] = Fv[m].y;
                ff[4 * m + 2] = Fv[m].z; ff[4 * m + 3] = Fv[m].w;
            }
#pragma unroll
            for (int j = 0; j < 16; j++)
                acc[j] += ff[4 + j] * wv.x + ff[3 + j] * wv.y
                        + ff[2 + j] * wv.z + ff[1 + j] * wv.w;
            wv = wn;
#pragma unroll
            for (int m = 0; m < 6; m++) Fv[m] = Fn[m];
        }
    }
    __syncthreads();

    // ---- per-chunk partials overlay the staging buffer ----
    float* redA = smem;                 // [16][128]
    float* redB = smem + 16 * 128;      // [16][256]
    if (active) {
        if (isA) {
#pragma unroll
            for (int j = 0; j < 16; j++) redA[j * 128 + tid] = acc[j];
        } else {
#pragma unroll
            for (int j = 0; j < 16; j++) redB[j * 256 + (tid - cA)] = acc[j];
        }
    }
    __syncthreads();

    // ---- stage-1 reduction: 8 partials per (tile,t) row ----
    if (tid < 256) {
        const int row = tid >> 3, k = tid & 7;
        float s = 0.f;
        if (row < 16) {
            for (int c = k; c < cA; c += 8) s += redA[row * 128 + c];
        } else {
            for (int c = k; c < cB; c += 8) s += redB[(row - 16) * 256 + c];
        }
        s2[row][k] = s;
    }
    __syncthreads();

    // ---- stage-2: this half's 32 sums; rank1 ships them to rank0 ----
    float s = 0.f;
    if (tid < 32) {
#pragma unroll
        for (int k = 0; k < 8; k++) s += s2[tid][k];
        if (half == 1) {
            unsigned int local =
                (unsigned int)__cvta_generic_to_shared(&sXfer[tid]);
            unsigned int remote;
            asm("mapa.shared::cluster.u32 %0, %1, %2;"
                : "=r"(remote) : "r"(local), "r"(0));
            asm volatile("st.shared::cluster.f32 [%0], %1;"
                         :: "r"(remote), "f"(s) : "memory");
        }
    }

    asm volatile("barrier.cluster.arrive.release.aligned;" ::: "memory");
    asm volatile("barrier.cluster.wait.acquire.aligned;"   ::: "memory");

    if (half == 0 && tid < 32) {
        const int t = (tid < 16) ? (t0A + tid) : (t0B + tid - 16);
        out[(t << 2) + e] = s + sXfer[tid];
    }
}

// ---------------------------------------------------------------------------
extern "C" void kernel_launch(void* const* d_in, const int* in_sizes, int n_in,
                              void* d_out, int out_size) {
    const float* Fx  = (const float*)d_in[0];   // [4,4,4,1024]
    const float* Dis = (const float*)d_in[1];   // [4,1024]
    const float* w0  = (const float*)d_in[2];   // [4,4,1024]
    float* out = (float*)d_out;                 // [1024*4 anti | 1024 gamma]

    const size_t dynBytes = (size_t)(SWOFF + 8 * 1024) * sizeof(float); // 66,304
    cudaFuncSetAttribute(k2, cudaFuncAttributeMaxDynamicSharedMemorySize,
                         (int)dynBytes);

    k1<<<8, 256>>>(Fx, Dis, w0);

    // k2 with programmatic dependent launch (overlaps with k1)
    cudaLaunchConfig_t cfg = {};
    cfg.gridDim = dim3(32, 4, 2);
    cfg.blockDim = dim3(320);
    cfg.dynamicSmemBytes = dynBytes;
    cfg.stream = 0;
    cudaLaunchAttribute attr[1];
    attr[0].id = cudaLaunchAttributeProgrammaticStreamSerialization;
    attr[0].val.programmaticStreamSerializationAllowed = 1;
    cfg.attrs = attr;
    cfg.numAttrs = 1;
    cudaLaunchKernelEx(&cfg, k2, Fx, out);
}

// round 7
// speedup vs baseline: 1.0200x; 1.0200x over previous
#include <cuda_runtime.h>
#include <cstdint>
#include <math.h>

#define T      1024
#define LRC    0.01f

// Scratch (device globals — allocation is forbidden)
__device__ float g_cw[16 * T];      // control weights [rs, n]
__device__ float g_epart[32];       // 8 cluster ranks x 4 e partials

// ---------------------------------------------------------------------------
// k1 (8-CTA cluster, 256 thr/CTA): fused err + cw + gamma vector.
// Fires the PDL trigger immediately so k2 can start staging Fx in parallel.
// ---------------------------------------------------------------------------
__global__ void __cluster_dims__(8, 1, 1) k1(const float* __restrict__ Fx,
                                             const float* __restrict__ Dis,
                                             const float* __restrict__ w0,
                                             float* __restrict__ out) {
    asm volatile("griddepcontrol.launch_dependents;");

    const int tid  = threadIdx.x;
    const int rank = blockIdx.x;
    const float4* w4  = (const float4*)w0;
    const float4* fx4 = (const float4*)Fx;

    // gamma vector: 2048 threads cover 1024 t's (independent work)
    {
        const int g = rank * 256 + tid;
        if (g < 1024) out[4096 + g] = powf(0.999f, (float)(1023 - g));
    }

    float acc[4] = {0.f, 0.f, 0.f, 0.f};
#pragma unroll
    for (int s = 0; s < 2; s++) {
        const int i4 = rank * 512 + s * 256 + tid;    // float4 index into w0
        const float4 w = w4[i4];
        const int rs = i4 >> 8, n4 = i4 & 255;
#pragma unroll
        for (int e = 0; e < 4; e++) {
            const float4 x = fx4[(rs << 10) + (e << 8) + n4];
            acc[e] += x.x * w.x + x.y * w.y + x.z * w.z + x.w * w.w;
        }
    }
#pragma unroll
    for (int o = 16; o; o >>= 1)
#pragma unroll
        for (int e = 0; e < 4; e++) acc[e] += __shfl_xor_sync(0xffffffffu, acc[e], o);

    __shared__ float sp[8][4];
    __shared__ float serr[4];
    if ((tid & 31) == 0)
#pragma unroll
        for (int e = 0; e < 4; e++) sp[tid >> 5][e] = acc[e];
    __syncthreads();
    if (tid < 4) {
        float s = 0.f;
#pragma unroll
        for (int wq = 0; wq < 8; wq++) s += sp[wq][tid];
        g_epart[rank * 4 + tid] = s;
    }

    asm volatile("barrier.cluster.arrive.release.aligned;" ::: "memory");
    asm volatile("barrier.cluster.wait.acquire.aligned;"   ::: "memory");

    if (tid < 4) {
        volatile const float* gp = g_epart;
        float s = 0.f;
#pragma unroll
        for (int r = 0; r < 8; r++) s += gp[r * 4 + tid];
        serr[tid] = Dis[tid * T + (T - 1)] - s;
    }
    __syncthreads();
    const float e0 = serr[0], e1 = serr[1], e2 = serr[2], e3 = serr[3];

    float4* cw4 = (float4*)g_cw;
#pragma unroll
    for (int s = 0; s < 2; s++) {
        const int i4 = rank * 512 + s * 256 + tid;
        float4 c = w4[i4];
        const int rs = i4 >> 8, n4 = i4 & 255;
        const float4 x0 = fx4[(rs << 10) + (0 << 8) + n4];
        const float4 x1 = fx4[(rs << 10) + (1 << 8) + n4];
        const float4 x2 = fx4[(rs << 10) + (2 << 8) + n4];
        const float4 x3 = fx4[(rs << 10) + (3 << 8) + n4];
        c.x += LRC * (x0.x * e0 + x1.x * e1 + x2.x * e2 + x3.x * e3);
        c.y += LRC * (x0.y * e0 + x1.y * e1 + x2.y * e2 + x3.y * e3);
        c.z += LRC * (x0.z * e0 + x1.z * e1 + x2.z * e2 + x3.z * e3);
        c.w += LRC * (x0.w * e0 + x1.w * e1 + x2.w * e2 + x3.w * e3);
        cw4[i4] = c;
    }
}

// ---------------------------------------------------------------------------
// k2: causal correlation + output.
// grid (32 pair-tiles, 4 e, 2 rs-halves), cluster (1,1,2), 640 thr, 66 KB smem
// -> 2 CTAs/SM = 40 warps/SM. Threads split the half's 8 rs rows into two
// sub-groups of 4 (tid<320 -> rows 0-3, else rows 4-7): per-thread work
// halves, eligible warps double. Partials combined in the smem reduction;
// rank1 ships its 32 sums to rank0 via DSMEM.
// ---------------------------------------------------------------------------
#define SFQ   1048            // sF row stride in floats (20 pad + 1024 + 4 tail)
#define NF4   262             // float4 per sF row
#define SWOFF (8 * SFQ)       // 8384: start of cw rows (8 rows of 1024)
#define RSEG  6144            // reduction floats per sub-group (16*128+16*256)

extern __shared__ float smem[];

__global__ void __launch_bounds__(640, 2) __cluster_dims__(1, 1, 2)
k2(const float* __restrict__ Fx, float* __restrict__ out) {
    __shared__ float s2[32][8];
    __shared__ float sXfer[32];

    const int tid  = threadIdx.x;
    const int b    = blockIdx.x;
    const int e    = blockIdx.y;
    const int half = blockIdx.z;                    // rs-half = cluster rank
    const int sub  = (tid >= 320);                  // qq sub-group
    const int tloc = tid - (sub << 8) - (sub << 6); // tid - sub*320
    const int t0A = b << 4, t0B = (63 - b) << 4;
    const int cA = (t0A + 16) >> 2;                 // 4..128 chunks for tile A
    const int cB = 260 - cA;                        // chunks for tile B
    const bool active = tloc < 260;
    const bool isA = tloc < cA;
    const int t0 = isA ? t0A : t0B;
    const int nb = (isA ? tloc : (tloc - cA)) << 2; // n-chunk base
    const int ab = 16 + t0 - nb;                    // aligned sF read base

    const float4 z4 = make_float4(0.f, 0.f, 0.f, 0.f);

    // ---- stage this half's 8 Fx rows (front zero-padded) — k1-independent ----
    float4* dF = (float4*)smem;
    for (int idx = tid; idx < 8 * NF4; idx += 640) {
        const int qq = idx / NF4, i = idx - qq * NF4;
        const int rs = (half << 3) + qq;
        float4 v = z4;
        if (i >= 5 && i < 261)
            v = ((const float4*)(Fx + (((rs << 2) + e) << 10)))[i - 5];
        dF[qq * NF4 + i] = v;
    }

    // ---- wait for k1's g_cw, then stage this half's 8 cw rows ----
    asm volatile("griddepcontrol.wait;" ::: "memory");
    float4* dW = (float4*)(smem + SWOFF);
    const float4* ws = (const float4*)(g_cw + (half << 3 << 10));
    for (int idx = tid; idx < 8 * 256; idx += 640)
        dW[idx] = ws[idx];
    __syncthreads();

    // ---- compute: 4 rs rows per thread (sub-group split) ----
    float acc[16];
#pragma unroll
    for (int j = 0; j < 16; j++) acc[j] = 0.f;

    if (active) {
        const float* wBase = &smem[SWOFF + (sub << 12) + nb];   // sub*4 rows
        const float* fBase = &smem[(sub << 2) * SFQ + ab];
#pragma unroll
        for (int qq = 0; qq < 4; qq++) {
            const float4 w = *(const float4*)(wBase + (qq << 10));
            const float4* F4 = (const float4*)(fBase + qq * SFQ);
            float ff[24];
#pragma unroll
            for (int m = 0; m < 6; m++) {
                const float4 v = F4[m];
                ff[4 * m + 0] = v.x; ff[4 * m + 1] = v.y;
                ff[4 * m + 2] = v.z; ff[4 * m + 3] = v.w;
            }
#pragma unroll
            for (int j = 0; j < 16; j++)
                acc[j] += ff[4 + j] * w.x + ff[3 + j] * w.y
                        + ff[2 + j] * w.z + ff[1 + j] * w.w;
        }
    }
    __syncthreads();

    // ---- per-chunk partials overlay the staging buffer ----
    // layout per sub-group: [16][128] (A) then [16][256] (B)
    float* redA = smem + sub * RSEG;
    float* redB = redA + 16 * 128;
    if (active) {
        if (isA) {
#pragma unroll
            for (int j = 0; j < 16; j++) redA[j * 128 + tloc] = acc[j];
        } else {
#pragma unroll
            for (int j = 0; j < 16; j++) redB[j * 256 + (tloc - cA)] = acc[j];
        }
    }
    __syncthreads();

    // ---- stage-1 reduction: 8 partials per (tile,t) row, both sub-groups ----
    if (tid < 256) {
        const int row = tid >> 3, k = tid & 7;
        float s = 0.f;
        if (row < 16) {
            for (int c = k; c < cA; c += 8)
                s += smem[row * 128 + c] + smem[RSEG + row * 128 + c];
        } else {
            const int r2 = row - 16;
            for (int c = k; c < cB; c += 8)
                s += smem[2048 + r2 * 256 + c] + smem[RSEG + 2048 + r2 * 256 + c];
        }
        s2[row][k] = s;
    }
    __syncthreads();

    // ---- stage-2: this half's 32 sums; rank1 ships them to rank0 ----
    float s = 0.f;
    if (tid < 32) {
#pragma unroll
        for (int k = 0; k < 8; k++) s += s2[tid][k];
        if (half == 1) {
            unsigned int local =
                (unsigned int)__cvta_generic_to_shared(&sXfer[tid]);
            unsigned int remote;
            asm("mapa.shared::cluster.u32 %0, %1, %2;"
                : "=r"(remote) : "r"(local), "r"(0));
            asm volatile("st.shared::cluster.f32 [%0], %1;"
                         :: "r"(remote), "f"(s) : "memory");
        }
    }

    asm volatile("barrier.cluster.arrive.release.aligned;" ::: "memory");
    asm volatile("barrier.cluster.wait.acquire.aligned;"   ::: "memory");

    if (half == 0 && tid < 32) {
        const int t = (tid < 16) ? (t0A + tid) : (t0B + tid - 16);
        out[(t << 2) + e] = s + sXfer[tid];
    }
}

// ---------------------------------------------------------------------------
extern "C" void kernel_launch(void* const* d_in, const int* in_sizes, int n_in,
                              void* d_out, int out_size) {
    const float* Fx  = (const float*)d_in[0];   // [4,4,4,1024]
    const float* Dis = (const float*)d_in[1];   // [4,1024]
    const float* w0  = (const float*)d_in[2];   // [4,4,1024]
    float* out = (float*)d_out;                 // [1024*4 anti | 1024 gamma]

    const size_t dynBytes = (size_t)(SWOFF + 8 * 1024) * sizeof(float); // 66,304
    cudaFuncSetAttribute(k2, cudaFuncAttributeMaxDynamicSharedMemorySize,
                         (int)dynBytes);

    k1<<<8, 256>>>(Fx, Dis, w0, out);

    // k2 with programmatic dependent launch (overlaps with k1)
    cudaLaunchConfig_t cfg = {};
    cfg.gridDim = dim3(32, 4, 2);
    cfg.blockDim = dim3(640);
    cfg.dynamicSmemBytes = dynBytes;
    cfg.stream = 0;
    cudaLaunchAttribute attr[1];
    attr[0].id = cudaLaunchAttributeProgrammaticStreamSerialization;
    attr[0].val.programmaticStreamSerializationAllowed = 1;
    cfg.attrs = attr;
    cfg.numAttrs = 1;
    cudaLaunchKernelEx(&cfg, k2, Fx, out);
}

// round 8
// speedup vs baseline: 1.0226x; 1.0025x over previous
#include <cuda_runtime.h>
#include <cstdint>
#include <math.h>

#define T      1024
#define LRC    0.01f

// Scratch (device globals — allocation is forbidden)
__device__ float g_cw[16 * T];      // control weights [rs, n]
__device__ float g_epart[32];       // 8 cluster ranks x 4 e partials

// ---------------------------------------------------------------------------
// k1 (8-CTA cluster, 256 thr/CTA): fused err + cw + gamma + out zero-init.
// Fires the PDL trigger immediately so k2 can start staging Fx in parallel.
// gamma/zero work is hidden inside the cluster-barrier gap.
// ---------------------------------------------------------------------------
__global__ void __cluster_dims__(8, 1, 1) k1(const float* __restrict__ Fx,
                                             const float* __restrict__ Dis,
                                             const float* __restrict__ w0,
                                             float* __restrict__ out) {
    asm volatile("griddepcontrol.launch_dependents;");

    const int tid  = threadIdx.x;
    const int rank = blockIdx.x;
    const float4* w4  = (const float4*)w0;
    const float4* fx4 = (const float4*)Fx;

    // ---- phase A: partial err dot products over this CTA's slice ----
    float acc[4] = {0.f, 0.f, 0.f, 0.f};
#pragma unroll
    for (int s = 0; s < 2; s++) {
        const int i4 = rank * 512 + s * 256 + tid;    // float4 index into w0
        const float4 w = w4[i4];
        const int rs = i4 >> 8, n4 = i4 & 255;
#pragma unroll
        for (int e = 0; e < 4; e++) {
            const float4 x = fx4[(rs << 10) + (e << 8) + n4];
            acc[e] += x.x * w.x + x.y * w.y + x.z * w.z + x.w * w.w;
        }
    }
#pragma unroll
    for (int o = 16; o; o >>= 1)
#pragma unroll
        for (int e = 0; e < 4; e++) acc[e] += __shfl_xor_sync(0xffffffffu, acc[e], o);

    __shared__ float sp[8][4];
    __shared__ float serr[4];
    if ((tid & 31) == 0)
#pragma unroll
        for (int e = 0; e < 4; e++) sp[tid >> 5][e] = acc[e];
    __syncthreads();
    if (tid < 4) {
        float s = 0.f;
#pragma unroll
        for (int wq = 0; wq < 8; wq++) s += sp[wq][tid];
        g_epart[rank * 4 + tid] = s;
    }

    asm volatile("barrier.cluster.arrive.release.aligned;" ::: "memory");

    // ---- barrier gap: zero out[0:4096) + gamma vector (independent work) ----
    {
        const int g = rank * 256 + tid;               // 0..2047
        if (g < 1024) {
            ((float4*)out)[g] = make_float4(0.f, 0.f, 0.f, 0.f);
            out[4096 + g] = __expf((float)(1023 - g) * -1.0005003e-3f);
        }
    }

    asm volatile("barrier.cluster.wait.acquire.aligned;" ::: "memory");

    if (tid < 4) {
        volatile const float* gp = g_epart;
        float s = 0.f;
#pragma unroll
        for (int r = 0; r < 8; r++) s += gp[r * 4 + tid];
        serr[tid] = Dis[tid * T + (T - 1)] - s;
    }
    __syncthreads();
    const float e0 = serr[0], e1 = serr[1], e2 = serr[2], e3 = serr[3];

    // ---- phase B: cw over the same slice (Fx/w0 L1-hot) ----
    float4* cw4 = (float4*)g_cw;
#pragma unroll
    for (int s = 0; s < 2; s++) {
        const int i4 = rank * 512 + s * 256 + tid;
        float4 c = w4[i4];
        const int rs = i4 >> 8, n4 = i4 & 255;
        const float4 x0 = fx4[(rs << 10) + (0 << 8) + n4];
        const float4 x1 = fx4[(rs << 10) + (1 << 8) + n4];
        const float4 x2 = fx4[(rs << 10) + (2 << 8) + n4];
        const float4 x3 = fx4[(rs << 10) + (3 << 8) + n4];
        c.x += LRC * (x0.x * e0 + x1.x * e1 + x2.x * e2 + x3.x * e3);
        c.y += LRC * (x0.y * e0 + x1.y * e1 + x2.y * e2 + x3.y * e3);
        c.z += LRC * (x0.z * e0 + x1.z * e1 + x2.z * e2 + x3.z * e3);
        c.w += LRC * (x0.w * e0 + x1.w * e1 + x2.w * e2 + x3.w * e3);
        cw4[i4] = c;
    }
}

// ---------------------------------------------------------------------------
// k2: causal correlation. grid (32 pair-tiles, 4 e, 2 rs-halves), 640 thr,
// 66 KB smem -> 2 CTAs/SM = 40 warps/SM. NO cluster: the two rs-halves
// combine via atomicAdd on out (exactly 2 contributors per element ->
// commutative -> bitwise deterministic; k1 zero-inits out). CTAs exit
// without waiting on a peer.
// ---------------------------------------------------------------------------
#define SFQ   1048            // sF row stride in floats (20 pad + 1024 + 4 tail)
#define NF4   262             // float4 per sF row
#define SWOFF (8 * SFQ)       // 8384: start of cw rows (8 rows of 1024)
#define RSEG  6144            // reduction floats per sub-group (16*128+16*256)

extern __shared__ float smem[];

__global__ void __launch_bounds__(640, 2)
k2(const float* __restrict__ Fx, float* __restrict__ out) {
    __shared__ float s2[32][20];

    const int tid  = threadIdx.x;
    const int b    = blockIdx.x;
    const int e    = blockIdx.y;
    const int half = blockIdx.z;                    // rs-half
    const int sub  = (tid >= 320);                  // qq sub-group
    const int tloc = tid - (sub << 8) - (sub << 6); // tid - sub*320
    const int t0A = b << 4, t0B = (63 - b) << 4;
    const int cA = (t0A + 16) >> 2;                 // 4..128 chunks for tile A
    const int cB = 260 - cA;                        // chunks for tile B
    const bool active = tloc < 260;
    const bool isA = tloc < cA;
    const int t0 = isA ? t0A : t0B;
    const int nb = (isA ? tloc : (tloc - cA)) << 2; // n-chunk base
    const int ab = 16 + t0 - nb;                    // aligned sF read base

    const float4 z4 = make_float4(0.f, 0.f, 0.f, 0.f);

    // ---- stage this half's 8 Fx rows (front zero-padded) — k1-independent ----
    float4* dF = (float4*)smem;
    for (int idx = tid; idx < 8 * NF4; idx += 640) {
        const int qq = idx / NF4, i = idx - qq * NF4;
        const int rs = (half << 3) + qq;
        float4 v = z4;
        if (i >= 5 && i < 261)
            v = ((const float4*)(Fx + (((rs << 2) + e) << 10)))[i - 5];
        dF[qq * NF4 + i] = v;
    }

    // ---- wait for k1's g_cw (and out zero-init), then stage 8 cw rows ----
    asm volatile("griddepcontrol.wait;" ::: "memory");
    float4* dW = (float4*)(smem + SWOFF);
    const float4* ws = (const float4*)(g_cw + (half << 3 << 10));
    for (int idx = tid; idx < 8 * 256; idx += 640)
        dW[idx] = ws[idx];
    __syncthreads();

    // ---- compute: 4 rs rows per thread (sub-group split) ----
    float acc[16];
#pragma unroll
    for (int j = 0; j < 16; j++) acc[j] = 0.f;

    if (active) {
        const float* wBase = &smem[SWOFF + (sub << 12) + nb];   // sub*4 rows
        const float* fBase = &smem[(sub << 2) * SFQ + ab];
#pragma unroll
        for (int qq = 0; qq < 4; qq++) {
            const float4 w = *(const float4*)(wBase + (qq << 10));
            const float4* F4 = (const float4*)(fBase + qq * SFQ);
            float ff[24];
#pragma unroll
            for (int m = 0; m < 6; m++) {
                const float4 v = F4[m];
                ff[4 * m + 0] = v.x; ff[4 * m + 1] = v.y;
                ff[4 * m + 2] = v.z; ff[4 * m + 3] = v.w;
            }
#pragma unroll
            for (int j = 0; j < 16; j++)
                acc[j] += ff[4 + j] * w.x + ff[3 + j] * w.y
                        + ff[2 + j] * w.z + ff[1 + j] * w.w;
        }
    }
    __syncthreads();

    // ---- per-chunk partials overlay the staging buffer ----
    // layout per sub-group: [16][128] (A) then [16][256] (B)
    float* redA = smem + sub * RSEG;
    float* redB = redA + 16 * 128;
    if (active) {
        if (isA) {
#pragma unroll
            for (int j = 0; j < 16; j++) redA[j * 128 + tloc] = acc[j];
        } else {
#pragma unroll
            for (int j = 0; j < 16; j++) redB[j * 256 + (tloc - cA)] = acc[j];
        }
    }
    __syncthreads();

    // ---- stage-1 reduction: 640 threads = 32 rows x 20 lanes ----
    {
        const int row = tid / 20;           // 0..31
        const int k   = tid - row * 20;     // 0..19
        float s = 0.f;
        if (row < 16) {
            for (int c = k; c < cA; c += 20)
                s += smem[row * 128 + c] + smem[RSEG + row * 128 + c];
        } else {
            const int r2 = row - 16;
            for (int c = k; c < cB; c += 20)
                s += smem[2048 + r2 * 256 + c] + smem[RSEG + 2048 + r2 * 256 + c];
        }
        s2[row][k] = s;
    }
    __syncthreads();

    // ---- stage-2: 32 final sums -> atomicAdd into out (2 halves/element) ----
    if (tid < 32) {
        float s = 0.f;
#pragma unroll
        for (int k = 0; k < 20; k++) s += s2[tid][k];
        const int t = (tid < 16) ? (t0A + tid) : (t0B + tid - 16);
        atomicAdd(&out[(t << 2) + e], s);
    }
}

// ---------------------------------------------------------------------------
extern "C" void kernel_launch(void* const* d_in, const int* in_sizes, int n_in,
                              void* d_out, int out_size) {
    const float* Fx  = (const float*)d_in[0];   // [4,4,4,1024]
    const float* Dis = (const float*)d_in[1];   // [4,1024]
    const float* w0  = (const float*)d_in[2];   // [4,4,1024]
    float* out = (float*)d_out;                 // [1024*4 anti | 1024 gamma]

    const size_t dynBytes = (size_t)(SWOFF + 8 * 1024) * sizeof(float); // 66,304
    cudaFuncSetAttribute(k2, cudaFuncAttributeMaxDynamicSharedMemorySize,
                         (int)dynBytes);

    k1<<<8, 256>>>(Fx, Dis, w0, out);

    // k2 with programmatic dependent launch (overlaps with k1)
    cudaLaunchConfig_t cfg = {};
    cfg.gridDim = dim3(32, 4, 2);
    cfg.blockDim = dim3(640);
    cfg.dynamicSmemBytes = dynBytes;
    cfg.stream = 0;
    cudaLaunchAttribute attr[1];
    attr[0].id = cudaLaunchAttributeProgrammaticStreamSerialization;
    attr[0].val.programmaticStreamSerializationAllowed = 1;
    cfg.attrs = attr;
    cfg.numAttrs = 1;
    cudaLaunchKernelEx(&cfg, k2, Fx, out);
}